// round 4
// baseline (speedup 1.0000x reference)
#include <cuda_runtime.h>
#include <math.h>

#define GN 8192
#define GF 512

// Scratch (allocation-free per harness rules)
__device__ __align__(16) float g_h[GN * GF];
__device__ float g_s1[GN];
__device__ float g_s2[GN];

// ---------------------------------------------------------------------------
// Kernel 1: h = inp @ W1 + b1   (8192x512 @ 512x512, fp32)
// Classic 128x128x8 SGEMM, 256 threads, 8x8 microtile.
// ---------------------------------------------------------------------------
__global__ __launch_bounds__(256) void gemm_h_kernel(
    const float* __restrict__ A,    // inp [8192][512]
    const float* __restrict__ B,    // W1  [512][512]
    const float* __restrict__ bias) // b1  [512]
{
    __shared__ float As[8][132];   // padded: conflict-free transposed stores
    __shared__ float Bs[8][128];

    const int tid = threadIdx.x;
    const int bx = blockIdx.x;     // N tile (0..3)
    const int by = blockIdx.y;     // M tile (0..63)
    const int tx = tid & 15;
    const int ty = tid >> 4;

    float acc[8][8];
#pragma unroll
    for (int i = 0; i < 8; i++)
#pragma unroll
        for (int j = 0; j < 8; j++) acc[i][j] = 0.f;

    const int a_r = tid >> 1;            // 0..127
    const int a_k = (tid & 1) * 4;       // 0 or 4
    const int b_k = tid >> 5;            // 0..7
    const int b_n = (tid & 31) * 4;      // 0..124

    const float* Aptr = A + (by * 128 + a_r) * GF + a_k;
    const float* Bptr = B + b_k * GF + bx * 128 + b_n;

    for (int k0 = 0; k0 < GF; k0 += 8) {
        float4 av = *(const float4*)(Aptr + k0);
        float4 bv = *(const float4*)(Bptr + k0 * GF);
        __syncthreads();  // previous compute done before overwrite
        As[a_k + 0][a_r] = av.x;
        As[a_k + 1][a_r] = av.y;
        As[a_k + 2][a_r] = av.z;
        As[a_k + 3][a_r] = av.w;
        *(float4*)&Bs[b_k][b_n] = bv;
        __syncthreads();

#pragma unroll
        for (int kk = 0; kk < 8; kk++) {
            float af[8], bf[8];
#pragma unroll
            for (int i = 0; i < 8; i++) af[i] = As[kk][ty * 8 + i];
#pragma unroll
            for (int j = 0; j < 8; j++) bf[j] = Bs[kk][tx * 8 + j];
#pragma unroll
            for (int i = 0; i < 8; i++)
#pragma unroll
                for (int j = 0; j < 8; j++) acc[i][j] += af[i] * bf[j];
        }
    }

    const int row0 = by * 128 + ty * 8;
    const int col0 = bx * 128 + tx * 8;
    float4 bb0 = *(const float4*)(bias + col0);
    float4 bb1 = *(const float4*)(bias + col0 + 4);
#pragma unroll
    for (int i = 0; i < 8; i++) {
        float4 v0, v1;
        v0.x = acc[i][0] + bb0.x; v0.y = acc[i][1] + bb0.y;
        v0.z = acc[i][2] + bb0.z; v0.w = acc[i][3] + bb0.w;
        v1.x = acc[i][4] + bb1.x; v1.y = acc[i][5] + bb1.y;
        v1.z = acc[i][6] + bb1.z; v1.w = acc[i][7] + bb1.w;
        *(float4*)&g_h[(row0 + i) * GF + col0]     = v0;
        *(float4*)&g_h[(row0 + i) * GF + col0 + 4] = v1;
    }
}

// ---------------------------------------------------------------------------
// Kernel 2: s1[i] = h[i]·a1, s2[i] = h[i]·a2   (one 128-thread block per row)
// ---------------------------------------------------------------------------
__global__ __launch_bounds__(128) void s1s2_kernel(
    const float* __restrict__ a1, const float* __restrict__ a2)
{
    const int row = blockIdx.x;
    const int tid = threadIdx.x;

    float4 hv = *(const float4*)(g_h + row * GF + tid * 4);
    float4 v1 = *(const float4*)(a1 + tid * 4);
    float4 v2 = *(const float4*)(a2 + tid * 4);
    float p1 = hv.x * v1.x + hv.y * v1.y + hv.z * v1.z + hv.w * v1.w;
    float p2 = hv.x * v2.x + hv.y * v2.y + hv.z * v2.z + hv.w * v2.w;

#pragma unroll
    for (int o = 16; o > 0; o >>= 1) {
        p1 += __shfl_down_sync(0xffffffffu, p1, o);
        p2 += __shfl_down_sync(0xffffffffu, p2, o);
    }
    __shared__ float r1[4], r2[4];
    const int lane = tid & 31, w = tid >> 5;
    if (lane == 0) { r1[w] = p1; r2[w] = p2; }
    __syncthreads();
    if (tid == 0) {
        g_s1[row] = r1[0] + r1[1] + r1[2] + r1[3];
        g_s2[row] = r2[0] + r2[1] + r2[2] + r2[3];
    }
}

// ---------------------------------------------------------------------------
// Kernel 3: fused masked-softmax attention + attn@h + elu.
// 32 output rows per block, 256 threads, j-tiles of 16.
// No max subtraction needed (scores ~N(0,1), exp can't overflow;
// masked entries give expf(-1e12)=0 exactly, matching the reference).
// ---------------------------------------------------------------------------
#define TM 32
#define TN 16

__global__ __launch_bounds__(256, 2) void gat_attn_kernel(
    const int* __restrict__ adj,
    const float* __restrict__ b2p,
    float* __restrict__ out)
{
    __shared__ __align__(16) float h_s[TN][GF];  // 32 KB
    __shared__ float P_s[TM][TN];                // 2 KB
    __shared__ float l_s[TM];
    __shared__ float s1_s[TM];

    const int tid = threadIdx.x;
    const int i0 = blockIdx.x * TM;
    const float b2 = *b2p;

    // MAC mapping: 4 rows x 16 strided cols per thread
    const int rgrp = tid >> 5;   // 0..7 -> rows rgrp*4 .. +3
    const int cg   = tid & 31;   // col lane (bank-aligned)
    float acc[4][16];
#pragma unroll
    for (int ri = 0; ri < 4; ri++)
#pragma unroll
        for (int k = 0; k < 16; k++) acc[ri][k] = 0.f;

    if (tid < TM) s1_s[tid] = g_s1[i0 + tid];

    // Score mapping: thread handles (sr, sc) and (sr, sc+8)
    const int sr = tid >> 3;     // 0..31
    const int sc = tid & 7;      // 0..7
    const int adjbase = (i0 + sr) * GN;
    float lpart = 0.f;           // per-thread partial row-sum of p (row sr)

    // Prefetch adj for tile 0
    int am0 = adj[adjbase + sc];
    int am1 = adj[adjbase + sc + 8];

    for (int j0 = 0; j0 < GN; j0 += TN) {
        __syncthreads();  // previous MAC finished; safe to overwrite smem

        // Load h tile [TN][512] = 2048 float4, 8 per thread
        const float4* hsrc = (const float4*)(g_h + j0 * GF);
        float4* hdst = (float4*)h_s;
#pragma unroll
        for (int t = 0; t < 8; t++) hdst[tid + t * 256] = hsrc[tid + t * 256];

        // Scores for this tile (adj already in registers)
        {
            const float sA = s1_s[sr];
            float e0 = sA + g_s2[j0 + sc] + b2;
            float e1 = sA + g_s2[j0 + sc + 8] + b2;
            e0 = e0 > 0.f ? e0 : 0.2f * e0;
            e1 = e1 > 0.f ? e1 : 0.2f * e1;
            float p0 = (am0 > 0) ? __expf(e0) : 0.f;
            float p1 = (am1 > 0) ? __expf(e1) : 0.f;
            lpart += p0 + p1;
            P_s[sr][sc]     = p0;
            P_s[sr][sc + 8] = p1;
        }

        // Prefetch adj for next tile (latency hidden under MAC below)
        if (j0 + TN < GN) {
            am0 = adj[adjbase + j0 + TN + sc];
            am1 = adj[adjbase + j0 + TN + sc + 8];
        }

        __syncthreads();  // h_s and P_s ready

        // MAC: acc[r][c] += P[r][jj] * h[jj][c]
#pragma unroll
        for (int jj = 0; jj < TN; jj++) {
            const float p0 = P_s[rgrp * 4 + 0][jj];
            const float p1 = P_s[rgrp * 4 + 1][jj];
            const float p2 = P_s[rgrp * 4 + 2][jj];
            const float p3 = P_s[rgrp * 4 + 3][jj];
#pragma unroll
            for (int k = 0; k < 16; k++) {
                const float hv = h_s[jj][cg + 32 * k];
                acc[0][k] += p0 * hv;
                acc[1][k] += p1 * hv;
                acc[2][k] += p2 * hv;
                acc[3][k] += p3 * hv;
            }
        }
    }

    // Reduce row sums l (8 lanes per row) and finalize
    {
        float v = lpart;
        v += __shfl_down_sync(0xffffffffu, v, 4, 8);
        v += __shfl_down_sync(0xffffffffu, v, 2, 8);
        v += __shfl_down_sync(0xffffffffu, v, 1, 8);
        if (sc == 0) l_s[sr] = v;
    }
    __syncthreads();

#pragma unroll
    for (int ri = 0; ri < 4; ri++) {
        const int row = rgrp * 4 + ri;
        const float inv = 1.0f / l_s[row];
#pragma unroll
        for (int k = 0; k < 16; k++) {
            float v = acc[ri][k] * inv;
            v = v > 0.f ? v : (expf(v) - 1.f);   // elu (alpha=1)
            out[(i0 + row) * GF + cg + 32 * k] = v;
        }
    }
}

// ---------------------------------------------------------------------------
extern "C" void kernel_launch(void* const* d_in, const int* in_sizes, int n_in,
                              void* d_out, int out_size)
{
    const float* inp = (const float*)d_in[0];   // [8192,512] f32
    const int*   adj = (const int*)d_in[1];     // [8192,8192] i32
    const float* W1  = (const float*)d_in[2];   // [512,512] f32
    const float* b1  = (const float*)d_in[3];   // [512] f32
    const float* a1  = (const float*)d_in[4];   // [512] f32
    const float* a2  = (const float*)d_in[5];   // [512] f32
    const float* b2  = (const float*)d_in[6];   // [] f32
    float* out = (float*)d_out;                 // [8192,512] f32

    (void)in_sizes; (void)n_in; (void)out_size;

    gemm_h_kernel<<<dim3(GF / 128, GN / 128), 256>>>(inp, W1, b1);
    s1s2_kernel<<<GN, 128>>>(a1, a2);
    gat_attn_kernel<<<GN / TM, 256>>>(adj, b2, out);
}

// round 5
// speedup vs baseline: 3.0004x; 3.0004x over previous
#include <cuda_runtime.h>
#include <cuda_bf16.h>
#include <math.h>

#define GN 8192
#define GF 512

// ---------------- device scratch (allocation-free) ----------------
__device__ __align__(16) float g_h [GN * GF];   // h = inp@W1+b1, fp32 [j][f]
__device__ __align__(16) float g_ht[GF * GN];   // h transposed, tf32-rounded fp32 [f][j]
__device__ float g_s1[GN], g_s2[GN];
__device__ float g_E1[GN], g_F1[GN], g_E2[GN], g_F2[GN];

// ---------------------------------------------------------------------------
// Kernel 1: h = inp @ W1 + b1   (8192x512 @ 512x512, fp32 SGEMM 128x128x8)
// ---------------------------------------------------------------------------
__global__ __launch_bounds__(256) void gemm_h_kernel(
    const float* __restrict__ A,    // inp [8192][512]
    const float* __restrict__ B,    // W1  [512][512]
    const float* __restrict__ bias) // b1  [512]
{
    __shared__ float As[8][132];
    __shared__ float Bs[8][128];

    const int tid = threadIdx.x;
    const int bx = blockIdx.x;
    const int by = blockIdx.y;
    const int tx = tid & 15;
    const int ty = tid >> 4;

    float acc[8][8];
#pragma unroll
    for (int i = 0; i < 8; i++)
#pragma unroll
        for (int j = 0; j < 8; j++) acc[i][j] = 0.f;

    const int a_r = tid >> 1;
    const int a_k = (tid & 1) * 4;
    const int b_k = tid >> 5;
    const int b_n = (tid & 31) * 4;

    const float* Aptr = A + (by * 128 + a_r) * GF + a_k;
    const float* Bptr = B + b_k * GF + bx * 128 + b_n;

    for (int k0 = 0; k0 < GF; k0 += 8) {
        float4 av = *(const float4*)(Aptr + k0);
        float4 bv = *(const float4*)(Bptr + k0 * GF);
        __syncthreads();
        As[a_k + 0][a_r] = av.x;
        As[a_k + 1][a_r] = av.y;
        As[a_k + 2][a_r] = av.z;
        As[a_k + 3][a_r] = av.w;
        *(float4*)&Bs[b_k][b_n] = bv;
        __syncthreads();

#pragma unroll
        for (int kk = 0; kk < 8; kk++) {
            float af[8], bf[8];
#pragma unroll
            for (int i = 0; i < 8; i++) af[i] = As[kk][ty * 8 + i];
#pragma unroll
            for (int j = 0; j < 8; j++) bf[j] = Bs[kk][tx * 8 + j];
#pragma unroll
            for (int i = 0; i < 8; i++)
#pragma unroll
                for (int j = 0; j < 8; j++) acc[i][j] += af[i] * bf[j];
        }
    }

    const int row0 = by * 128 + ty * 8;
    const int col0 = bx * 128 + tx * 8;
    float4 bb0 = *(const float4*)(bias + col0);
    float4 bb1 = *(const float4*)(bias + col0 + 4);
#pragma unroll
    for (int i = 0; i < 8; i++) {
        float4 v0, v1;
        v0.x = acc[i][0] + bb0.x; v0.y = acc[i][1] + bb0.y;
        v0.z = acc[i][2] + bb0.z; v0.w = acc[i][3] + bb0.w;
        v1.x = acc[i][4] + bb1.x; v1.y = acc[i][5] + bb1.y;
        v1.z = acc[i][6] + bb1.z; v1.w = acc[i][7] + bb1.w;
        *(float4*)&g_h[(row0 + i) * GF + col0]     = v0;
        *(float4*)&g_h[(row0 + i) * GF + col0 + 4] = v1;
    }
}

// ---------------------------------------------------------------------------
// Kernel 2: transpose g_h -> g_ht [f][j], rounding to tf32 (rna)
// ---------------------------------------------------------------------------
__global__ __launch_bounds__(256) void transpose_kernel()
{
    __shared__ float t[32][33];
    const int tx = threadIdx.x & 31;
    const int ty = threadIdx.x >> 5;          // 0..7
    const int j0 = blockIdx.x * 32;
    const int f0 = blockIdx.y * 32;

#pragma unroll
    for (int i = 0; i < 4; i++)
        t[ty + i * 8][tx] = g_h[(j0 + ty + i * 8) * GF + f0 + tx];
    __syncthreads();
#pragma unroll
    for (int i = 0; i < 4; i++) {
        float x = t[tx][ty + i * 8];
        unsigned u;
        asm("cvt.rna.tf32.f32 %0, %1;" : "=r"(u) : "f"(x));
        g_ht[(f0 + ty + i * 8) * GN + j0 + tx] = __uint_as_float(u);
    }
}

// ---------------------------------------------------------------------------
// Kernel 3: s1[i] = h[i]·a1, s2[i] = h[i]·a2
// ---------------------------------------------------------------------------
__global__ __launch_bounds__(128) void s1s2_kernel(
    const float* __restrict__ a1, const float* __restrict__ a2)
{
    const int row = blockIdx.x;
    const int tid = threadIdx.x;

    float4 hv = *(const float4*)(g_h + row * GF + tid * 4);
    float4 v1 = *(const float4*)(a1 + tid * 4);
    float4 v2 = *(const float4*)(a2 + tid * 4);
    float p1 = hv.x * v1.x + hv.y * v1.y + hv.z * v1.z + hv.w * v1.w;
    float p2 = hv.x * v2.x + hv.y * v2.y + hv.z * v2.z + hv.w * v2.w;

#pragma unroll
    for (int o = 16; o > 0; o >>= 1) {
        p1 += __shfl_down_sync(0xffffffffu, p1, o);
        p2 += __shfl_down_sync(0xffffffffu, p2, o);
    }
    __shared__ float r1[4], r2[4];
    const int lane = tid & 31, w = tid >> 5;
    if (lane == 0) { r1[w] = p1; r2[w] = p2; }
    __syncthreads();
    if (tid == 0) {
        g_s1[row] = r1[0] + r1[1] + r1[2] + r1[3];
        g_s2[row] = r2[0] + r2[1] + r2[2] + r2[3];
    }
}

// ---------------------------------------------------------------------------
// Kernel 4: factorized-exp precompute. x = s1_i + s2_j + b2.
//   exp(leaky(x)) = (x>0) ? E1_i*E2_j : F1_i*F2_j,  x>0 <=> E1_i*E2_j > 1
// ---------------------------------------------------------------------------
__global__ __launch_bounds__(256) void prep_kernel(const float* __restrict__ b2p)
{
    const int i = blockIdx.x * 256 + threadIdx.x;
    const float b2 = *b2p;
    const float x1 = g_s1[i] + b2;
    const float x2 = g_s2[i];
    g_E1[i] = __expf(x1);
    g_F1[i] = __expf(0.2f * x1);
    g_E2[i] = __expf(x2);
    g_F2[i] = __expf(0.2f * x2);
}

// ---------------------------------------------------------------------------
// Kernel 5: fused masked-softmax attention + attn@h + elu, tf32 mma.sync.
// 32 rows/CTA, j-tiles of 32, 8 warps: warp w owns output cols [w*64, w*64+64).
// hT tile [512][32] f32 (stride 36 for conflict-free fragment loads) via cp.async.
// ---------------------------------------------------------------------------
#define AM 32
#define AK 32
#define HTS 36                                   // padded f32 stride
#define SMEM_HT  (GF * HTS * 4)                  // 73728 B
#define SMEM_P   (AM * HTS * 4)                  // 4608 B
#define SMEM_TOT (SMEM_HT + SMEM_P + 96 * 4)     // 78720 B

__global__ __launch_bounds__(256, 2) void gat_attn_mma(
    const int* __restrict__ adj,
    float* __restrict__ out)
{
    extern __shared__ char smraw[];
    float* hT  = (float*)smraw;
    float* Ps  = (float*)(smraw + SMEM_HT);
    float* E1s = (float*)(smraw + SMEM_HT + SMEM_P);
    float* F1s = E1s + 32;
    float* ls  = E1s + 64;

    const int tid  = threadIdx.x;
    const int w    = tid >> 5;                   // warp 0..7
    const int lane = tid & 31;
    const int gid  = lane >> 2;                  // 0..7
    const int tig  = lane & 3;                   // 0..3
    const int i0   = blockIdx.x * AM;

    if (tid < AM) { E1s[tid] = g_E1[i0 + tid]; F1s[tid] = g_F1[i0 + tid]; }

    float acc[2][8][4];
#pragma unroll
    for (int mt = 0; mt < 2; mt++)
#pragma unroll
        for (int nt = 0; nt < 8; nt++)
#pragma unroll
            for (int q = 0; q < 4; q++) acc[mt][nt][q] = 0.f;

    // score mapping: warp w, lane c -> rows {w, 8+w, 16+w, 24+w}, col j0+c
    const int c = lane;
    float lacc[4] = {0.f, 0.f, 0.f, 0.f};
    int am4[4];
#pragma unroll
    for (int rr = 0; rr < 4; rr++)
        am4[rr] = adj[(i0 + rr * 8 + w) * GN + c];   // prefetch tile 0

    const unsigned ht_smem = (unsigned)__cvta_generic_to_shared(hT);

    __syncthreads();   // E1s/F1s visible

    for (int j0 = 0; j0 < GN; j0 += AK) {
        // ---- async hT tile load: 512 rows x 32 f32 (128B/row), 16 x 16B/thread
#pragma unroll
        for (int t = 0; t < 16; t++) {
            const int v = tid + t * 256;
            const int f = v >> 3, part = v & 7;
            const float* src = g_ht + f * GN + j0 + part * 4;
            const unsigned dst = ht_smem + (unsigned)(f * HTS + part * 4) * 4u;
            asm volatile("cp.async.ca.shared.global [%0], [%1], 16;\n"
                         :: "r"(dst), "l"(src));
        }
        asm volatile("cp.async.commit_group;\n");

        // ---- scores for this tile (adj already in registers, zero MUFU)
        {
            const float E2c = g_E2[j0 + c];
            const float F2c = g_F2[j0 + c];
#pragma unroll
            for (int rr = 0; rr < 4; rr++) {
                const int row = rr * 8 + w;
                const float u  = E1s[row] * E2c;
                const float vv = F1s[row] * F2c;
                float p = (am4[rr] > 0) ? (u > 1.f ? u : vv) : 0.f;
                unsigned pt;
                asm("cvt.rna.tf32.f32 %0, %1;" : "=r"(pt) : "f"(p));
                const float pr = __uint_as_float(pt);
                lacc[rr] += pr;                    // l consistent with numerator
                Ps[row * HTS + c] = pr;
            }
        }

        asm volatile("cp.async.wait_group 0;\n" ::: "memory");
        __syncthreads();                           // hT + Ps ready

        // ---- prefetch adj for next tile (hidden under MMA)
        if (j0 + AK < GN) {
#pragma unroll
            for (int rr = 0; rr < 4; rr++)
                am4[rr] = adj[(i0 + rr * 8 + w) * GN + j0 + AK + c];
        }

        // ---- MAC: 4 k-steps of m16n8k8 tf32
#pragma unroll
        for (int ks = 0; ks < 4; ks++) {
            const int k0 = ks * 8;
            unsigned a[2][4];
#pragma unroll
            for (int mt = 0; mt < 2; mt++) {
                const float* ap = Ps + (mt * 16 + gid) * HTS + k0 + tig;
                a[mt][0] = __float_as_uint(ap[0]);
                a[mt][1] = __float_as_uint(ap[8 * HTS]);
                a[mt][2] = __float_as_uint(ap[4]);
                a[mt][3] = __float_as_uint(ap[8 * HTS + 4]);
            }
#pragma unroll
            for (int nt = 0; nt < 8; nt++) {
                const float* bp = hT + (w * 64 + nt * 8 + gid) * HTS + k0 + tig;
                const unsigned b0 = __float_as_uint(bp[0]);
                const unsigned b1 = __float_as_uint(bp[4]);
                asm volatile(
                    "mma.sync.aligned.m16n8k8.row.col.f32.tf32.tf32.f32 "
                    "{%0,%1,%2,%3}, {%4,%5,%6,%7}, {%8,%9}, {%0,%1,%2,%3};\n"
                    : "+f"(acc[0][nt][0]), "+f"(acc[0][nt][1]),
                      "+f"(acc[0][nt][2]), "+f"(acc[0][nt][3])
                    : "r"(a[0][0]), "r"(a[0][1]), "r"(a[0][2]), "r"(a[0][3]),
                      "r"(b0), "r"(b1));
                asm volatile(
                    "mma.sync.aligned.m16n8k8.row.col.f32.tf32.tf32.f32 "
                    "{%0,%1,%2,%3}, {%4,%5,%6,%7}, {%8,%9}, {%0,%1,%2,%3};\n"
                    : "+f"(acc[1][nt][0]), "+f"(acc[1][nt][1]),
                      "+f"(acc[1][nt][2]), "+f"(acc[1][nt][3])
                    : "r"(a[1][0]), "r"(a[1][1]), "r"(a[1][2]), "r"(a[1][3]),
                      "r"(b0), "r"(b1));
            }
        }
        __syncthreads();                           // MAC done, smem reusable
    }

    // ---- row-sum reduction: each row owned by exactly one warp
#pragma unroll
    for (int rr = 0; rr < 4; rr++) {
        float v = lacc[rr];
        v += __shfl_down_sync(0xffffffffu, v, 16);
        v += __shfl_down_sync(0xffffffffu, v, 8);
        v += __shfl_down_sync(0xffffffffu, v, 4);
        v += __shfl_down_sync(0xffffffffu, v, 2);
        v += __shfl_down_sync(0xffffffffu, v, 1);
        if (lane == 0) ls[rr * 8 + w] = v;
    }
    __syncthreads();

    // ---- epilogue: normalize + elu + store
#pragma unroll
    for (int mt = 0; mt < 2; mt++) {
        const int r1 = mt * 16 + gid;
        const int r2 = r1 + 8;
        const float inv1 = 1.0f / ls[r1];
        const float inv2 = 1.0f / ls[r2];
#pragma unroll
        for (int nt = 0; nt < 8; nt++) {
            const int col = w * 64 + nt * 8 + tig * 2;
            float o0 = acc[mt][nt][0] * inv1;
            float o1 = acc[mt][nt][1] * inv1;
            float o2 = acc[mt][nt][2] * inv2;
            float o3 = acc[mt][nt][3] * inv2;
            o0 = o0 > 0.f ? o0 : (__expf(o0) - 1.f);
            o1 = o1 > 0.f ? o1 : (__expf(o1) - 1.f);
            o2 = o2 > 0.f ? o2 : (__expf(o2) - 1.f);
            o3 = o3 > 0.f ? o3 : (__expf(o3) - 1.f);
            *(float2*)&out[(i0 + r1) * GF + col] = make_float2(o0, o1);
            *(float2*)&out[(i0 + r2) * GF + col] = make_float2(o2, o3);
        }
    }
}

// ---------------------------------------------------------------------------
extern "C" void kernel_launch(void* const* d_in, const int* in_sizes, int n_in,
                              void* d_out, int out_size)
{
    const float* inp = (const float*)d_in[0];
    const int*   adj = (const int*)d_in[1];
    const float* W1  = (const float*)d_in[2];
    const float* b1  = (const float*)d_in[3];
    const float* a1  = (const float*)d_in[4];
    const float* a2  = (const float*)d_in[5];
    const float* b2  = (const float*)d_in[6];
    float* out = (float*)d_out;

    (void)in_sizes; (void)n_in; (void)out_size;

    cudaFuncSetAttribute(gat_attn_mma,
                         cudaFuncAttributeMaxDynamicSharedMemorySize, SMEM_TOT);

    gemm_h_kernel<<<dim3(GF / 128, GN / 128), 256>>>(inp, W1, b1);
    transpose_kernel<<<dim3(GN / 32, GF / 32), 256>>>();
    s1s2_kernel<<<GN, 128>>>(a1, a2);
    prep_kernel<<<GN / 256, 256>>>(b2);
    gat_attn_mma<<<GN / AM, 256, SMEM_TOT>>>(adj, out);
}